// round 17
// baseline (speedup 1.0000x reference)
#include <cuda_runtime.h>
#include <cuda_fp16.h>
#include <math.h>

#define IMW 1024
#define IMH 1024
#define NB  8
#define OW  128
#define OH  32
#define LW  160          // luma tile cols: global x in [x0-16, x0+144)
#define LH  62           // luma tile rows: global y in [y0-15, y0+47)
#define SWH 160          // shared row stride in halves (320 bytes)
#define NT  256
// smem: (62+32+32)*160*2 = 40320 B -> 4 CTAs/SM
#define SMEM_BYTES ((LH + OH + OH) * SWH * 2)

#define PRMT54(a, b) __byte_perm((a), (b), 0x5432)

// fp16x2 immediates (same weight both lanes).
// 31-tap gaussian (sigma=8), normalized, k=0..30 (center 15)
__device__ constexpr unsigned G31X2[31] = {
    0x20A520A5u, 0x21D421D4u, 0x23322332u, 0x24602460u, 0x253C253Cu, 0x262B262Bu,
    0x27282728u, 0x28162816u, 0x28982898u, 0x29162916u, 0x298B298Bu, 0x29F229F2u,
    0x2A482A48u, 0x2A882A88u, 0x2AAF2AAFu, 0x2ABD2ABDu, 0x2AAF2AAFu, 0x2A882A88u,
    0x2A482A48u, 0x29F229F2u, 0x298B298Bu, 0x29162916u, 0x28982898u, 0x28162816u,
    0x27282728u, 0x262B262Bu, 0x253C253Cu, 0x24602460u, 0x23322332u, 0x21D421D4u,
    0x20A520A5u
};
// 7-tap gaussian (sigma=1.5), normalized
__device__ constexpr unsigned G7X2[7] = {
    0x28B028B0u, 0x2F1F2F1Fu, 0x32F032F0u, 0x34553455u,
    0x32F032F0u, 0x2F1F2F1Fu, 0x28B028B0u
};

__device__ __forceinline__ __half2 hc(unsigned b) {
    __half2_raw r;
    r.x = (unsigned short)(b & 0xFFFFu);
    r.y = (unsigned short)(b >> 16);
    return __half2(r);
}

__global__ __launch_bounds__(NT, 4)
void clarity_texture_kernel(const float* __restrict__ x,
                            const float* __restrict__ clar,
                            const float* __restrict__ tex,
                            float* __restrict__ out) {
    extern __shared__ __half smem[];
    __half* sLuma = smem;                 // LH x SWH
    __half* sV31  = smem + LH * SWH;      // OH x SWH  (vertical 31-tap)
    __half* sV7   = sV31 + OH * SWH;      // OH x SWH  (vertical 7-tap)

    const int tid = threadIdx.x;
    const int x0  = blockIdx.x * OW;
    const int y0  = blockIdx.y * OH;
    const int b   = blockIdx.z;

    const float ca = tanhf(*clar) * 0.5f;
    const float ta = tanhf(*tex) * 0.3f;

    const size_t plane = (size_t)IMH * IMW;
    const float* xb = x + (size_t)b * 3 * plane;
    float* ob = out + (size_t)b * 3 * plane;

    // ---- Phase 1: luma tile with halo (fp16 store), float4 global loads ----
    for (int i = tid; i < LH * (LW / 4); i += NT) {
        int row = i / (LW / 4);
        int cc  = i % (LW / 4);
        int gy  = y0 - 15 + row;
        int gx  = x0 - 16 + cc * 4;
        float4 l4 = make_float4(0.f, 0.f, 0.f, 0.f);
        if ((unsigned)gy < IMH && (unsigned)gx < IMW) {
            size_t idx = (size_t)gy * IMW + gx;
            float4 r4 = *(const float4*)&xb[idx];
            float4 g4 = *(const float4*)&xb[idx + plane];
            float4 b4 = *(const float4*)&xb[idx + 2 * plane];
            l4.x = 0.2126f * r4.x + 0.7152f * g4.x + 0.0722f * b4.x;
            l4.y = 0.2126f * r4.y + 0.7152f * g4.y + 0.0722f * b4.y;
            l4.z = 0.2126f * r4.z + 0.7152f * g4.z + 0.0722f * b4.z;
            l4.w = 0.2126f * r4.w + 0.7152f * g4.w + 0.0722f * b4.w;
        }
        __half2 h0 = __floats2half2_rn(l4.x, l4.y);
        __half2 h1 = __floats2half2_rn(l4.z, l4.w);
        uint2 pk;
        pk.x = *(unsigned*)&h0;
        pk.y = *(unsigned*)&h1;
        *(uint2*)&sLuma[row * SWH + cc * 4] = pk;
    }
    __syncthreads();

    // ---- Phase 2: vertical 31-tap AND 7-tap blurs, HFMA2, 2 cols x 4 rows ----
    for (int s = tid; s < (SWH / 2) * (OH / 4); s += NT) {   // 80*8 = 640
        int c  = s % (SWH / 2);
        int r0 = (s / (SWH / 2)) * 4;
        __half2 a[4], w[4];
        #pragma unroll
        for (int o = 0; o < 4; o++) { a[o] = hc(0u); w[o] = hc(0u); }
        #pragma unroll
        for (int k = 0; k < 34; k++) {
            __half2 v = *(const __half2*)&sLuma[(r0 + k) * SWH + 2 * c];
            #pragma unroll
            for (int o = 0; o < 4; o++) {
                int i31 = k - o;
                if (i31 >= 0 && i31 < 31) a[o] = __hfma2(v, hc(G31X2[i31]), a[o]);
                int j7 = k - 12 - o;                 // 7-tap: luma rows r0+o+12..+18
                if (j7 >= 0 && j7 < 7)    w[o] = __hfma2(v, hc(G7X2[j7]), w[o]);
            }
        }
        #pragma unroll
        for (int o = 0; o < 4; o++) {
            *(__half2*)&sV31[(r0 + o) * SWH + 2 * c] = a[o];
            *(__half2*)&sV7 [(r0 + o) * SWH + 2 * c] = w[o];
        }
    }
    __syncthreads();

    // ---- Phase 3: horizontal blurs (HFMA2 + PRMT pairs) + combine + clip ----
    for (int s = tid; s < OH * (OW / 8); s += NT) {   // 32*16 = 512 items
        int strip = s & 15;
        int r     = s >> 4;
        int c0    = strip * 8;

        __half2 acc31[4], acc7[4];
        #pragma unroll
        for (int p = 0; p < 4; p++) { acc31[p] = hc(0u); acc7[p] = hc(0u); }

        // 31-tap: output pair p lanes = cols (c0+2p, c0+2p+1).
        // Tap position m (halves from c0): lanes (v[m], v[m+1]); k = m-1-2p.
        {
            const uint4* p31 = (const uint4*)&sV31[r * SWH + c0];
            uint4 cur = p31[0];
            #pragma unroll
            for (int chk = 0; chk < 5; chk++) {
                uint4 nxt = (chk < 4) ? p31[chk + 1] : make_uint4(0u, 0u, 0u, 0u);
                unsigned T[8];
                T[0] = cur.x; T[2] = cur.y; T[4] = cur.z; T[6] = cur.w;
                T[1] = PRMT54(cur.x, cur.y);
                T[3] = PRMT54(cur.y, cur.z);
                T[5] = PRMT54(cur.z, cur.w);
                T[7] = PRMT54(cur.w, nxt.x);
                #pragma unroll
                for (int q = 0; q < 8; q++) {
                    int m = chk * 8 + q;
                    #pragma unroll
                    for (int p = 0; p < 4; p++) {
                        int k = m - 1 - 2 * p;
                        if (k >= 0 && k < 31)
                            acc31[p] = __hfma2(hc(T[q]), hc(G31X2[k]), acc31[p]);
                    }
                }
                cur = nxt;
            }
        }

        // 7-tap: base col c0+8; output pair p taps at offset m = 5+2p+j (j=0..6).
        {
            const uint4* p7 = (const uint4*)&sV7[r * SWH + c0 + 8];
            uint4 cur = p7[0];
            #pragma unroll
            for (int chk = 0; chk < 3; chk++) {
                uint4 nxt = (chk < 2) ? p7[chk + 1] : make_uint4(0u, 0u, 0u, 0u);
                unsigned T[8];
                T[0] = cur.x; T[2] = cur.y; T[4] = cur.z; T[6] = cur.w;
                T[1] = PRMT54(cur.x, cur.y);
                T[3] = PRMT54(cur.y, cur.z);
                T[5] = PRMT54(cur.z, cur.w);
                T[7] = PRMT54(cur.w, nxt.x);
                #pragma unroll
                for (int q = 0; q < 8; q++) {
                    int m = chk * 8 + q;
                    #pragma unroll
                    for (int p = 0; p < 4; p++) {
                        int j = m - 5 - 2 * p;
                        if (j >= 0 && j < 7)
                            acc7[p] = __hfma2(hc(T[q]), hc(G7X2[j]), acc7[p]);
                    }
                }
                cur = nxt;
            }
        }

        // unpack accumulators to fp32
        float a31[8], a7[8];
        #pragma unroll
        for (int p = 0; p < 4; p++) {
            float2 f = __half22float2(acc31[p]);
            a31[2 * p] = f.x; a31[2 * p + 1] = f.y;
            float2 g = __half22float2(acc7[p]);
            a7[2 * p] = g.x; a7[2 * p + 1] = g.y;
        }

        // center luma (8 halves, one LDS.128)
        float lum[8];
        {
            uint4 u = *(const uint4*)&sLuma[(r + 15) * SWH + c0 + 16];
            float2 f;
            f = __half22float2(*(__half2*)&u.x); lum[0]=f.x; lum[1]=f.y;
            f = __half22float2(*(__half2*)&u.y); lum[2]=f.x; lum[3]=f.y;
            f = __half22float2(*(__half2*)&u.z); lum[4]=f.x; lum[5]=f.y;
            f = __half22float2(*(__half2*)&u.w); lum[6]=f.x; lum[7]=f.y;
        }

        float ratio[8];
        #pragma unroll
        for (int o = 0; o < 8; o++) {
            float le = lum[o] + ca * (lum[o] - a31[o]) + ta * (lum[o] - a7[o]);
            ratio[o] = __fdividef(le + 1e-6f, lum[o] + 1e-6f);
        }

        int gy = y0 + r;
        int gx = x0 + c0;
        size_t idx = (size_t)gy * IMW + gx;
        #pragma unroll
        for (int ch = 0; ch < 3; ch++) {
            size_t o0 = idx + (size_t)ch * plane;
            float4 xa = *(const float4*)&xb[o0];
            float4 xc = *(const float4*)&xb[o0 + 4];
            float4 ra, rc;
            ra.x = __saturatef(xa.x * ratio[0]); ra.y = __saturatef(xa.y * ratio[1]);
            ra.z = __saturatef(xa.z * ratio[2]); ra.w = __saturatef(xa.w * ratio[3]);
            rc.x = __saturatef(xc.x * ratio[4]); rc.y = __saturatef(xc.y * ratio[5]);
            rc.z = __saturatef(xc.z * ratio[6]); rc.w = __saturatef(xc.w * ratio[7]);
            *(float4*)&ob[o0]     = ra;
            *(float4*)&ob[o0 + 4] = rc;
        }
    }
}

extern "C" void kernel_launch(void* const* d_in, const int* in_sizes, int n_in,
                              void* d_out, int out_size) {
    const float* x    = (const float*)d_in[0];
    const float* clar = (const float*)d_in[1];
    const float* tex  = (const float*)d_in[2];
    float* out = (float*)d_out;

    cudaFuncSetAttribute(clarity_texture_kernel,
                         cudaFuncAttributeMaxDynamicSharedMemorySize, SMEM_BYTES);

    dim3 grid(IMW / OW, IMH / OH, NB);
    clarity_texture_kernel<<<grid, NT, SMEM_BYTES>>>(x, clar, tex, out);
}